// round 9
// baseline (speedup 1.0000x reference)
#include <cuda_runtime.h>
#include <cstdint>

// Problem shape (fixed by setup_inputs)
constexpr int Hh     = 512;
constexpr int Ww     = 512;
constexpr int PLANES = 64;             // B*C = 16*4
constexpr int NPIX   = Hh * Ww;        // 262144 per plane
constexpr int W4     = Ww / 4;         // 128 vec4 per row
constexpr int TPB    = 256;
constexpr int RPT    = 4;              // rows per thread
constexpr int BANDS  = Hh / (2 * RPT); // 64 bands of 8 rows
constexpr int TOTAL_BLOCKS = PLANES * BANDS;  // 4096

// Scratch accumulators (allocation-free: __device__ globals, zero-initialized)
// NOTE: the ce+edge accumulator is spread over PLANES addresses so no single
// L2 address receives more than 64 fp64 RMWs (the LTS atomic ALU serializes
// per-address; 4096-deep chains were the hidden ~40us tail in prior rounds).
__device__ double   g_accv[PLANES];    // ce + edge numerator, per plane
__device__ double   g_isum[PLANES];    // sum of y
__device__ double   g_rsum[PLANES];    // sum of r = 1 - sigmoid
__device__ double   g_rysum[PLANES];   // sum of r over y==1 pixels
__device__ unsigned g_count;

__device__ __forceinline__ float ex2f(float x) { float y; asm("ex2.approx.f32 %0, %1;" : "=f"(y) : "f"(x)); return y; }
__device__ __forceinline__ float lg2f(float x) { float y; asm("lg2.approx.f32 %0, %1;" : "=f"(y) : "f"(x)); return y; }
__device__ __forceinline__ float rcpf(float x) { float y; asm("rcp.approx.f32 %0, %1;" : "=f"(y) : "f"(x)); return y; }

// Pack four 0/1 int32 values into 4 bytes of one register (3 PRMT)
__device__ __forceinline__ unsigned pack01(int4 v) {
    unsigned t0 = __byte_perm((unsigned)v.x, (unsigned)v.y, 0x0040);
    unsigned t1 = __byte_perm((unsigned)v.z, (unsigned)v.w, 0x0040);
    return __byte_perm(t0, t1, 0x5410);   // [x0, y0, z0, w0]
}

// byte k of v (value 0..255) as float, via exponent-splice: PRMT + FADD
template <int K>
__device__ __forceinline__ float bytef(unsigned v) {
    const unsigned sel = 0x7440u | (unsigned)K;          // [vK, 00, 00, 4B]
    return __uint_as_float(__byte_perm(v, 0x4B000000u, sel)) - 8388608.0f;
}
// 1 + byte k of v, same trick with bias folded in
template <int K>
__device__ __forceinline__ float bytef1p(unsigned v) {
    const unsigned sel = 0x7440u | (unsigned)K;
    return __uint_as_float(__byte_perm(v, 0x4B000000u, sel)) - 8388607.0f;
}

__global__ __launch_bounds__(TPB, 4) void fused_k(const float* __restrict__ cmap,
                                                  const int*   __restrict__ gt,
                                                  float*       __restrict__ out) {
    const int plane = blockIdx.y;
    const int band  = blockIdx.x;
    const int tid   = threadIdx.x;
    const int w4    = tid & (W4 - 1);            // vec4 column 0..127
    const int rgrp  = tid >> 7;                  // 0 or 1
    const int r0    = band * (2 * RPT) + rgrp * RPT;  // first row of this thread
    const int lane  = tid & 31;

    const int4*   __restrict__ gp  = reinterpret_cast<const int4*>(gt)     + (size_t)plane * (NPIX / 4);
    const float4* __restrict__ cp  = reinterpret_cast<const float4*>(cmap) + (size_t)plane * (NPIX / 4);
    const int*    __restrict__ gts = gt + (size_t)plane * NPIX;

    const int4 zero4 = make_int4(0, 0, 0, 0);
    const unsigned FULL = 0xFFFFFFFFu;

    // ================= FRONT-BATCHED LOADS (max MLP) =================
    int4 g[RPT + 2];
    g[0] = (r0 > 0) ? __ldg(gp + (r0 - 1) * W4 + w4) : zero4;
#pragma unroll
    for (int i = 0; i < RPT; ++i)
        g[i + 1] = __ldg(gp + (r0 + i) * W4 + w4);
    g[RPT + 1] = (r0 + RPT < Hh) ? __ldg(gp + (r0 + RPT) * W4 + w4) : zero4;

    float4 xr[RPT];
#pragma unroll
    for (int i = 0; i < RPT; ++i)
        xr[i] = __ldg(cp + (r0 + i) * W4 + w4);

    int lf[RPT], rg[RPT];
#pragma unroll
    for (int i = 0; i < RPT; ++i) {
        const int h = r0 + i;
        lf[i] = (lane == 0  && w4 > 0)      ? __ldg(gts + h * Ww + w4 * 4 - 1) : 0;
        rg[i] = (lane == 31 && w4 < W4 - 1) ? __ldg(gts + h * Ww + w4 * 4 + 4) : 0;
    }

    // ================= COMPUTE PHASE (registers only) =================
    unsigned pk[RPT + 2];
#pragma unroll
    for (int i = 0; i < RPT + 2; ++i) pk[i] = pack01(g[i]);

    float acc_lg = 0.f;   // sum of lg2(1+e^x) * (1 + edge)   [lg2 units]
    float xysum  = 0.f;   // sum of x*y
    float rsum   = 0.f;   // sum of r = 1 - sigmoid
    float rysum  = 0.f;   // sum of r*y
    int   icnt   = 0;     // sum of y

#pragma unroll
    for (int i = 0; i < RPT; ++i) {
        const unsigned cpk = pk[i + 1];
        const unsigned ppk = pk[i];
        const unsigned npk = pk[i + 2];

        // horizontal neighbors: adjacent lanes own adjacent vec4 columns
        unsigned lsh = __shfl_up_sync(FULL, cpk, 1);
        unsigned rsh = __shfl_down_sync(FULL, cpk, 1);
        if (lane == 0)  lsh = ((unsigned)lf[i]) << 24;
        if (lane == 31) rsh = (unsigned)rg[i];
        const unsigned lpk = __funnelshift_l(lsh, cpk, 8);   // (cpk<<8) | (lsh>>24)
        const unsigned rpk = __funnelshift_r(cpk, rsh, 8);   // (cpk>>8) | (rsh<<24)

        // packed 5-point dilation / erosion / boundary, 4 px per op
        const unsigned orv = (cpk | ppk | npk) | lpk | rpk;
        const unsigned anv = (cpk & ppk & npk) & lpk & rpk;
        const unsigned e   = orv & ~anv;                     // each byte in {0,1}

        icnt += __popc(cpk);                                 // 0/1 bytes -> sum(y)

        const float xx[4] = {xr[i].x, xr[i].y, xr[i].z, xr[i].w};
#pragma unroll
        for (int k = 0; k < 4; ++k) {
            const float x  = xx[k];
            const float p  = ex2f(x * 1.4426950408889634f);   // e^x
            const float s  = 1.f + p;
            const float r  = rcpf(s);                          // 1 - sigmoid(x)
            const float t  = lg2f(s);                          // softplus(x)/ln2

            float yf, ef1;
            switch (k) {  // compile-time: pick PRMT selector
                case 0: yf = bytef<0>(cpk); ef1 = bytef1p<0>(e); break;
                case 1: yf = bytef<1>(cpk); ef1 = bytef1p<1>(e); break;
                case 2: yf = bytef<2>(cpk); ef1 = bytef1p<2>(e); break;
                default: yf = bytef<3>(cpk); ef1 = bytef1p<3>(e); break;
            }

            acc_lg = fmaf(t, ef1, acc_lg);    // sp*(1+edge) in lg2 units
            xysum  = fmaf(x, yf, xysum);      // x*y
            rsum  += r;
            rysum  = fmaf(r, yf, rysum);
        }
    }

    // ---- warp + block reduction ----
#pragma unroll
    for (int off = 16; off > 0; off >>= 1) {
        acc_lg += __shfl_down_sync(FULL, acc_lg, off);
        xysum  += __shfl_down_sync(FULL, xysum, off);
        rsum   += __shfl_down_sync(FULL, rsum, off);
        rysum  += __shfl_down_sync(FULL, rysum, off);
        icnt   += __shfl_down_sync(FULL, icnt, off);
    }

    __shared__ float sA[TPB / 32], sX[TPB / 32], sR[TPB / 32], sY[TPB / 32];
    __shared__ int   sC[TPB / 32];
    const int wid = tid >> 5;
    if (lane == 0) { sA[wid] = acc_lg; sX[wid] = xysum; sR[wid] = rsum; sY[wid] = rysum; sC[wid] = icnt; }
    __syncthreads();

    if (tid == 0) {
        float ta = 0.f, tx = 0.f, tr = 0.f, ty = 0.f;
        int   tc = 0;
#pragma unroll
        for (int w = 0; w < TPB / 32; ++w) { ta += sA[w]; tx += sX[w]; tr += sR[w]; ty += sY[w]; tc += sC[w]; }
        const float comb = 0.6931471805599453f * ta - tx;   // ce + edge numerator
        atomicAdd(&g_accv[plane],  (double)comb);           // 64 RMWs/address max
        atomicAdd(&g_rsum[plane],  (double)tr);
        atomicAdd(&g_rysum[plane], (double)ty);
        atomicAdd(&g_isum[plane],  (double)tc);

        __threadfence();
        const unsigned done = atomicAdd(&g_count, 1u);
        if (done == TOTAL_BLOCKS - 1) {
            __threadfence();
            volatile double* vi = g_isum;
            volatile double* vr = g_rsum;
            volatile double* vy = g_rysum;
            volatile double* va = g_accv;

            const double N      = (double)PLANES * (double)NPIX;
            const double SMOOTH = 0.0001;
            double dice = 0.0, accs = 0.0;
#pragma unroll
            for (int p = 0; p < PLANES; ++p) {
                const double inter = vi[p] - vy[p];                 // sum(y*pred)
                const double jsum  = (double)NPIX - vr[p];          // sum(pred)
                const double sc    = (2.0 * inter + SMOOTH) / (vi[p] + jsum + SMOOTH);
                dice += (1.0 - sc);
                accs += va[p];
            }
            dice *= (1.0 / 16.0);                 // mean over batch, sum over classes
            out[0] = (float)(accs / N + dice);

            // reset for the next graph replay
#pragma unroll
            for (int p = 0; p < PLANES; ++p) { vi[p] = 0.0; vr[p] = 0.0; vy[p] = 0.0; va[p] = 0.0; }
            g_count = 0u;
        }
    }
}

extern "C" void kernel_launch(void* const* d_in, const int* in_sizes, int n_in,
                              void* d_out, int out_size) {
    const float* cmap = (const float*)d_in[0];
    const int*   gt   = (const int*)d_in[1];
    float*       out  = (float*)d_out;

    dim3 grid(BANDS, PLANES);
    fused_k<<<grid, TPB>>>(cmap, gt, out);
}

// round 14
// speedup vs baseline: 1.0455x; 1.0455x over previous
#include <cuda_runtime.h>
#include <cstdint>

// Problem shape (fixed by setup_inputs)
constexpr int Hh     = 512;
constexpr int Ww     = 512;
constexpr int PLANES = 64;             // B*C = 16*4
constexpr int NPIX   = Hh * Ww;        // 262144 per plane
constexpr int W4     = Ww / 4;         // 128 vec4 per row
constexpr int TPB    = 256;
constexpr int ROWS_B = 8;              // rows per block tile
constexpr int BANDS  = Hh / ROWS_B;    // 64
constexpr int TOTAL_BLOCKS = PLANES * BANDS;  // 4096

// smem packed-gt tile: 10 rows (8 + 2 halo) x (1 pad + 128 data + 1 pad) u32 words
constexpr int ROW_W  = 130;            // words per smem row
constexpr int TILE_W = 10 * ROW_W;     // 1300 words = 5200 B

// Scratch accumulators (allocation-free: __device__ globals, zero-initialized)
__device__ double   g_accv[PLANES];    // ce + edge numerator, per plane
__device__ double   g_isum[PLANES];    // sum of y
__device__ double   g_rsum[PLANES];    // sum of r = 1 - sigmoid
__device__ double   g_rysum[PLANES];   // sum of r over y==1 pixels
__device__ unsigned g_count;

__device__ __forceinline__ float tanhf_a(float x) { float y; asm("tanh.approx.f32 %0, %1;" : "=f"(y) : "f"(x)); return y; }
__device__ __forceinline__ float lg2f(float x)    { float y; asm("lg2.approx.f32 %0, %1;"  : "=f"(y) : "f"(x)); return y; }

// Pack four 0/1 int32 values into 4 bytes of one register (3 PRMT)
__device__ __forceinline__ unsigned pack01(int4 v) {
    unsigned t0 = __byte_perm((unsigned)v.x, (unsigned)v.y, 0x0040);
    unsigned t1 = __byte_perm((unsigned)v.z, (unsigned)v.w, 0x0040);
    return __byte_perm(t0, t1, 0x5410);   // [x0, y0, z0, w0] little-endian bytes
}

__global__ __launch_bounds__(TPB) void fused_k(const float* __restrict__ cmap,
                                               const int*   __restrict__ gt,
                                               float*       __restrict__ out) {
    const int plane = blockIdx.y;
    const int band  = blockIdx.x;
    const int tid   = threadIdx.x;

    const int4*   __restrict__ gp = reinterpret_cast<const int4*>(gt)     + (size_t)plane * (NPIX / 4);
    const float4* __restrict__ cp = reinterpret_cast<const float4*>(cmap) + (size_t)plane * (NPIX / 4);

    __shared__ unsigned tile[TILE_W];

    // ---- zero the horizontal pad words (20 of them) ----
    if (tid < 20) {
        const int r = tid >> 1;
        tile[r * ROW_W + ((tid & 1) ? (ROW_W - 1) : 0)] = 0u;
    }

    // ---- cooperative pack of gt rows band*8-1 .. band*8+8 into smem ----
    const int r0g = band * ROWS_B - 1;    // global row of smem row 0
#pragma unroll
    for (int j = 0; j < 5; ++j) {
        const int item = tid + j * TPB;   // 0..1279
        const int row  = item >> 7;       // 0..9
        const int col  = item & 127;
        const int gr   = r0g + row;
        unsigned w = 0u;
        if ((unsigned)gr < (unsigned)Hh)
            w = pack01(__ldg(gp + gr * W4 + col));
        tile[row * ROW_W + 1 + col] = w;
    }

    // ---- front-batch this thread's 4 cmap rows while smem fills ----
    const int w4c  = tid & 127;           // vec4 column
    const int rg2  = tid >> 7;            // 0 or 1
    const int lr0  = 1 + rg2 * 4;         // first local (smem) row
    const int gr0  = band * ROWS_B + rg2 * 4;

    float4 xr[4];
#pragma unroll
    for (int i = 0; i < 4; ++i)
        xr[i] = __ldg(cp + (gr0 + i) * W4 + w4c);

    __syncthreads();

    // ---- compute: branch-free stencil from smem + tanh/lg2 chain ----
    float lgsum = 0.f;   // sum of lg2(r) * (1 + edge)   (negative)
    float xysum = 0.f;   // sum of x*y
    float rsum  = 0.f;   // sum of r
    float rysum = 0.f;   // sum of r*y
    int   icnt  = 0;     // sum of y

    unsigned ppk = tile[(lr0 - 1) * ROW_W + 1 + w4c];
    unsigned cpk = tile[ lr0      * ROW_W + 1 + w4c];

#pragma unroll
    for (int i = 0; i < 4; ++i) {
        const int cw = (lr0 + i) * ROW_W + 1 + w4c;
        const unsigned npk = tile[cw + ROW_W];
        const unsigned lw  = tile[cw - 1];
        const unsigned rw  = tile[cw + 1];

        const unsigned lpk = __funnelshift_l(lw, cpk, 8);   // (cpk<<8) | (lw>>24)
        const unsigned rpk = __funnelshift_r(cpk, rw, 8);   // (cpk>>8) | (rw<<24)

        const unsigned orv = (cpk | ppk | npk) | lpk | rpk;
        const unsigned anv = (cpk & ppk & npk) & lpk & rpk;
        const unsigned e   = orv & ~anv;                    // bytes in {0,1}

        icnt += __popc(cpk);

        const float xx[4] = {xr[i].x, xr[i].y, xr[i].z, xr[i].w};
#pragma unroll
        for (int k = 0; k < 4; ++k) {
            const float x   = xx[k];
            const float th  = tanhf_a(0.5f * x);
            const float r   = fmaf(-0.5f, th, 0.5f);        // 1 - sigmoid(x)
            const float lgr = lg2f(r);                       // = -softplus(x)/ln2

            lgsum += lgr;
            rsum  += r;
            if (e & (0xFFu << (8 * k))) lgsum += lgr;        // edge doubles sp
            if (cpk & (0xFFu << (8 * k))) { xysum += x; rysum += r; }
        }
        ppk = cpk; cpk = npk;
    }

    // ---- warp + block reduction ----
    const unsigned FULL = 0xFFFFFFFFu;
#pragma unroll
    for (int off = 16; off > 0; off >>= 1) {
        lgsum += __shfl_down_sync(FULL, lgsum, off);
        xysum += __shfl_down_sync(FULL, xysum, off);
        rsum  += __shfl_down_sync(FULL, rsum, off);
        rysum += __shfl_down_sync(FULL, rysum, off);
        icnt  += __shfl_down_sync(FULL, icnt, off);
    }

    __shared__ float sA[TPB / 32], sX[TPB / 32], sR[TPB / 32], sY[TPB / 32];
    __shared__ int   sC[TPB / 32];
    const int wid  = tid >> 5;
    const int lane = tid & 31;
    if (lane == 0) { sA[wid] = lgsum; sX[wid] = xysum; sR[wid] = rsum; sY[wid] = rysum; sC[wid] = icnt; }
    __syncthreads();

    if (tid == 0) {
        float ta = 0.f, tx = 0.f, tr = 0.f, ty = 0.f;
        int   tc = 0;
#pragma unroll
        for (int w = 0; w < TPB / 32; ++w) { ta += sA[w]; tx += sX[w]; tr += sR[w]; ty += sY[w]; tc += sC[w]; }
        // ce+edge numerator: sum sp*(1+e) - sum x*y ; sp = -ln2 * lgr
        const float comb = -0.6931471805599453f * ta - tx;
        atomicAdd(&g_accv[plane],  (double)comb);
        atomicAdd(&g_rsum[plane],  (double)tr);
        atomicAdd(&g_rysum[plane], (double)ty);
        atomicAdd(&g_isum[plane],  (double)tc);

        __threadfence();
        const unsigned done = atomicAdd(&g_count, 1u);
        if (done == TOTAL_BLOCKS - 1) {
            __threadfence();
            volatile double* vi = g_isum;
            volatile double* vr = g_rsum;
            volatile double* vy = g_rysum;
            volatile double* va = g_accv;

            const double N      = (double)PLANES * (double)NPIX;
            const double SMOOTH = 0.0001;
            double dice = 0.0, accs = 0.0;
#pragma unroll
            for (int p = 0; p < PLANES; ++p) {
                const double inter = vi[p] - vy[p];                 // sum(y*pred)
                const double jsum  = (double)NPIX - vr[p];          // sum(pred)
                const double sc    = (2.0 * inter + SMOOTH) / (vi[p] + jsum + SMOOTH);
                dice += (1.0 - sc);
                accs += va[p];
            }
            dice *= (1.0 / 16.0);                 // mean over batch, sum over classes
            out[0] = (float)(accs / N + dice);

            // reset for the next graph replay
#pragma unroll
            for (int p = 0; p < PLANES; ++p) { vi[p] = 0.0; vr[p] = 0.0; vy[p] = 0.0; va[p] = 0.0; }
            g_count = 0u;
        }
    }
}

extern "C" void kernel_launch(void* const* d_in, const int* in_sizes, int n_in,
                              void* d_out, int out_size) {
    const float* cmap = (const float*)d_in[0];
    const int*   gt   = (const int*)d_in[1];
    float*       out  = (float*)d_out;

    dim3 grid(BANDS, PLANES);
    fused_k<<<grid, TPB>>>(cmap, gt, out);
}

// round 15
// speedup vs baseline: 2.4012x; 2.2968x over previous
#include <cuda_runtime.h>
#include <cstdint>

// Problem shape (fixed by setup_inputs)
constexpr int Hh     = 512;
constexpr int Ww     = 512;
constexpr int PLANES = 64;             // B*C = 16*4
constexpr int NPIX   = Hh * Ww;        // 262144 per plane
constexpr int W4     = Ww / 4;         // 128 vec4 per row
constexpr int TPB    = 256;
constexpr int ROWS_B = 8;              // rows per block tile
constexpr int BANDS  = Hh / ROWS_B;    // 64

// smem packed-gt tile: 10 rows (8 + 2 halo) x (1 pad + 128 data + 1 pad) u32 words
constexpr int ROW_W  = 130;            // words per smem row
constexpr int TILE_W = 10 * ROW_W;     // 1300 words = 5200 B

// Accumulator slots: 4 per plane -> max 16 same-address RMWs (BANDS/4).
// No single-address deep atomic chain anywhere (the LTS atomic ALU
// serializes per address; 4096-deep counted atomics were the invariant
// across all ~70us variants).
constexpr int SLOTS = PLANES * 4;      // 256

__device__ double g_accv[SLOTS];       // ce + edge numerator
__device__ double g_isum[SLOTS];       // sum of y
__device__ double g_rsum[SLOTS];       // sum of r = 1 - sigmoid
__device__ double g_rysum[SLOTS];      // sum of r over y==1 pixels

__device__ __forceinline__ float tanhf_a(float x) { float y; asm("tanh.approx.f32 %0, %1;" : "=f"(y) : "f"(x)); return y; }
__device__ __forceinline__ float lg2f(float x)    { float y; asm("lg2.approx.f32 %0, %1;"  : "=f"(y) : "f"(x)); return y; }

// Pack four 0/1 int32 values into 4 bytes of one register (3 PRMT)
__device__ __forceinline__ unsigned pack01(int4 v) {
    unsigned t0 = __byte_perm((unsigned)v.x, (unsigned)v.y, 0x0040);
    unsigned t1 = __byte_perm((unsigned)v.z, (unsigned)v.w, 0x0040);
    return __byte_perm(t0, t1, 0x5410);   // [x0, y0, z0, w0] little-endian bytes
}

__global__ __launch_bounds__(TPB) void main_k(const float* __restrict__ cmap,
                                              const int*   __restrict__ gt) {
    const int plane = blockIdx.y;
    const int band  = blockIdx.x;
    const int tid   = threadIdx.x;

    const int4*   __restrict__ gp = reinterpret_cast<const int4*>(gt)     + (size_t)plane * (NPIX / 4);
    const float4* __restrict__ cp = reinterpret_cast<const float4*>(cmap) + (size_t)plane * (NPIX / 4);

    __shared__ unsigned tile[TILE_W];

    // ---- zero the horizontal pad words (20 of them) ----
    if (tid < 20) {
        const int r = tid >> 1;
        tile[r * ROW_W + ((tid & 1) ? (ROW_W - 1) : 0)] = 0u;
    }

    // ---- cooperative pack of gt rows band*8-1 .. band*8+8 into smem ----
    const int r0g = band * ROWS_B - 1;    // global row of smem row 0
#pragma unroll
    for (int j = 0; j < 5; ++j) {
        const int item = tid + j * TPB;   // 0..1279
        const int row  = item >> 7;       // 0..9
        const int col  = item & 127;
        const int gr   = r0g + row;
        unsigned w = 0u;
        if ((unsigned)gr < (unsigned)Hh)
            w = pack01(__ldg(gp + gr * W4 + col));
        tile[row * ROW_W + 1 + col] = w;
    }

    // ---- front-batch this thread's 4 cmap rows while smem fills ----
    const int w4c  = tid & 127;           // vec4 column
    const int rg2  = tid >> 7;            // 0 or 1
    const int lr0  = 1 + rg2 * 4;         // first local (smem) row
    const int gr0  = band * ROWS_B + rg2 * 4;

    float4 xr[4];
#pragma unroll
    for (int i = 0; i < 4; ++i)
        xr[i] = __ldg(cp + (gr0 + i) * W4 + w4c);

    __syncthreads();

    // ---- compute: branch-free stencil from smem + tanh/lg2 chain ----
    float lgsum = 0.f;   // sum of lg2(r) * (1 + edge)   (negative)
    float xysum = 0.f;   // sum of x*y
    float rsum  = 0.f;   // sum of r
    float rysum = 0.f;   // sum of r*y
    int   icnt  = 0;     // sum of y

    unsigned ppk = tile[(lr0 - 1) * ROW_W + 1 + w4c];
    unsigned cpk = tile[ lr0      * ROW_W + 1 + w4c];

#pragma unroll
    for (int i = 0; i < 4; ++i) {
        const int cw = (lr0 + i) * ROW_W + 1 + w4c;
        const unsigned npk = tile[cw + ROW_W];
        const unsigned lw  = tile[cw - 1];
        const unsigned rw  = tile[cw + 1];

        const unsigned lpk = __funnelshift_l(lw, cpk, 8);   // (cpk<<8) | (lw>>24)
        const unsigned rpk = __funnelshift_r(cpk, rw, 8);   // (cpk>>8) | (rw<<24)

        const unsigned orv = (cpk | ppk | npk) | lpk | rpk;
        const unsigned anv = (cpk & ppk & npk) & lpk & rpk;
        const unsigned e   = orv & ~anv;                    // bytes in {0,1}

        icnt += __popc(cpk);

        const float xx[4] = {xr[i].x, xr[i].y, xr[i].z, xr[i].w};
#pragma unroll
        for (int k = 0; k < 4; ++k) {
            const float x   = xx[k];
            const float th  = tanhf_a(0.5f * x);
            const float r   = fmaf(-0.5f, th, 0.5f);        // 1 - sigmoid(x)
            const float lgr = lg2f(r);                       // = -softplus(x)/ln2

            lgsum += lgr;
            rsum  += r;
            if (e & (0xFFu << (8 * k))) lgsum += lgr;        // edge doubles sp
            if (cpk & (0xFFu << (8 * k))) { xysum += x; rysum += r; }
        }
        ppk = cpk; cpk = npk;
    }

    // ---- warp + block reduction ----
    const unsigned FULL = 0xFFFFFFFFu;
#pragma unroll
    for (int off = 16; off > 0; off >>= 1) {
        lgsum += __shfl_down_sync(FULL, lgsum, off);
        xysum += __shfl_down_sync(FULL, xysum, off);
        rsum  += __shfl_down_sync(FULL, rsum, off);
        rysum += __shfl_down_sync(FULL, rysum, off);
        icnt  += __shfl_down_sync(FULL, icnt, off);
    }

    __shared__ float sA[TPB / 32], sX[TPB / 32], sR[TPB / 32], sY[TPB / 32];
    __shared__ int   sC[TPB / 32];
    const int wid  = tid >> 5;
    const int lane = tid & 31;
    if (lane == 0) { sA[wid] = lgsum; sX[wid] = xysum; sR[wid] = rsum; sY[wid] = rysum; sC[wid] = icnt; }
    __syncthreads();

    if (tid == 0) {
        float ta = 0.f, tx = 0.f, tr = 0.f, ty = 0.f;
        int   tc = 0;
#pragma unroll
        for (int w = 0; w < TPB / 32; ++w) { ta += sA[w]; tx += sX[w]; tr += sR[w]; ty += sY[w]; tc += sC[w]; }
        // ce+edge numerator: sum sp*(1+e) - sum x*y ; sp = -ln2 * lgr
        const float comb = -0.6931471805599453f * ta - tx;
        const int   slot = plane * 4 + (band & 3);           // <=16 RMWs per address
        atomicAdd(&g_accv[slot],  (double)comb);
        atomicAdd(&g_rsum[slot],  (double)tr);
        atomicAdd(&g_rysum[slot], (double)ty);
        atomicAdd(&g_isum[slot],  (double)tc);
    }
}

__global__ void fin_k(float* __restrict__ out) {
    const int t = threadIdx.x;
    __shared__ double red[64];

    double contrib = 0.0;
    if (t < PLANES) {
        double ac = 0.0, is = 0.0, rs = 0.0, ry = 0.0;
#pragma unroll
        for (int s = 0; s < 4; ++s) {
            ac += g_accv[t * 4 + s];
            is += g_isum[t * 4 + s];
            rs += g_rsum[t * 4 + s];
            ry += g_rysum[t * 4 + s];
        }
        const double N      = (double)PLANES * (double)NPIX;
        const double SMOOTH = 0.0001;
        const double inter  = is - ry;                 // sum(y*pred)
        const double jsum   = (double)NPIX - rs;       // sum(pred)
        const double sc     = (2.0 * inter + SMOOTH) / (is + jsum + SMOOTH);
        contrib = (1.0 - sc) * (1.0 / 16.0) + ac / N;  // plane's dice + ce/edge share
    }

    // reduce 64 doubles: warp shuffle within 2 warps, then cross-warp
    const unsigned FULL = 0xFFFFFFFFu;
#pragma unroll
    for (int off = 16; off > 0; off >>= 1)
        contrib += __shfl_down_sync(FULL, contrib, off);
    if (t < PLANES && (t & 31) == 0) red[t >> 5] = contrib;
    __syncthreads();
    if (t == 0) out[0] = (float)(red[0] + red[1]);

    // reset accumulators for the next graph replay
    if (t < SLOTS) { g_accv[t] = 0.0; g_isum[t] = 0.0; g_rsum[t] = 0.0; g_rysum[t] = 0.0; }
}

extern "C" void kernel_launch(void* const* d_in, const int* in_sizes, int n_in,
                              void* d_out, int out_size) {
    const float* cmap = (const float*)d_in[0];
    const int*   gt   = (const int*)d_in[1];
    float*       out  = (float*)d_out;

    dim3 grid(BANDS, PLANES);
    main_k<<<grid, TPB>>>(cmap, gt);
    fin_k<<<1, SLOTS>>>(out);
}